// round 7
// baseline (speedup 1.0000x reference)
#include <cuda_runtime.h>
#include <cstdint>

// Problem constants
#define BATCH 16384
#define TT    10
#define II    184
#define HH    128

// Derived
#define K1 (II + HH)      // 312
#define K2 (256 + HH)     // 384
#define CK 24             // k-chunk rows staged in SMEM (divides 312 and 384)

// ---------------------------------------------------------------------------
// Scratch (device globals; no allocation allowed)
// ---------------------------------------------------------------------------
__device__ float g_WT1[2 * K1 * 512];     // [dir][k][gate]  (gate = g*128 + j)
__device__ float g_B1 [2 * 512];
__device__ float g_WT2[2 * K2 * 512];
__device__ float g_B2 [2 * 512];
__device__ float g_O1 [BATCH * TT * 256]; // layer1 output (fwd|bwd concat)
__device__ float g_O2 [BATCH * TT * 256]; // layer2 output
__device__ float g_FC1T[512 * 64];        // fc1_w transposed: [k][j]

// ---------------------------------------------------------------------------
// f32x2 packed-math helpers (FFMA2 path, sm_100+)
// ---------------------------------------------------------------------------
typedef unsigned long long ull;

__device__ __forceinline__ ull pack2(float lo, float hi) {
    ull r;
    asm("mov.b64 %0, {%1, %2};" : "=l"(r) : "f"(lo), "f"(hi));
    return r;
}
__device__ __forceinline__ ull fma2(ull a, ull b, ull c) {
    ull d;
    asm("fma.rn.f32x2 %0, %1, %2, %3;" : "=l"(d) : "l"(a), "l"(b), "l"(c));
    return d;
}
__device__ __forceinline__ float2 unpack2(ull v) {
    float2 f;
    asm("mov.b64 {%0, %1}, %2;" : "=f"(f.x), "=f"(f.y) : "l"(v));
    return f;
}

__device__ __forceinline__ float sigf(float x) {
    return 1.0f / (1.0f + __expf(-x));
}
__device__ __forceinline__ float tanh_fast(float x) {
    return 2.0f / (1.0f + __expf(-2.0f * x)) - 1.0f;
}

// cp.async helpers
__device__ __forceinline__ void cp16(float* dst_smem, const float* src) {
    unsigned saddr = (unsigned)__cvta_generic_to_shared(dst_smem);
    asm volatile("cp.async.cg.shared.global [%0], [%1], 16;"
                 :: "r"(saddr), "l"(src));
}
__device__ __forceinline__ void cp_commit() {
    asm volatile("cp.async.commit_group;");
}
__device__ __forceinline__ void cp_wait0() {
    asm volatile("cp.async.wait_group 0;" ::: "memory");
}

// ---------------------------------------------------------------------------
// Fused prep (single launch): build WT[dir][k][512] for both layers,
// bias sums, and fc1 transpose.
// ---------------------------------------------------------------------------
__global__ void prep_all(const float* __restrict__ wih1f, const float* __restrict__ whh1f,
                         const float* __restrict__ bih1f, const float* __restrict__ bhh1f,
                         const float* __restrict__ wih1b, const float* __restrict__ whh1b,
                         const float* __restrict__ bih1b, const float* __restrict__ bhh1b,
                         const float* __restrict__ wih2f, const float* __restrict__ whh2f,
                         const float* __restrict__ bih2f, const float* __restrict__ bhh2f,
                         const float* __restrict__ wih2b, const float* __restrict__ whh2b,
                         const float* __restrict__ bih2b, const float* __restrict__ bhh2b,
                         const float* __restrict__ fc1w,
                         float* __restrict__ wt1, float* __restrict__ b1,
                         float* __restrict__ wt2, float* __restrict__ b2,
                         float* __restrict__ fct)
{
    const int stride = gridDim.x * blockDim.x;
    const int tid0 = blockIdx.x * blockDim.x + threadIdx.x;

    // layer1: 2 dirs, K1*512 each
    for (int idx = tid0; idx < 2 * K1 * 512; idx += stride) {
        int dir = idx / (K1 * 512);
        int r   = idx - dir * (K1 * 512);
        int k = r >> 9, g = r & 511;
        const float* wih = dir ? wih1b : wih1f;
        const float* whh = dir ? whh1b : whh1f;
        wt1[idx] = (k < II) ? wih[g * II + k] : whh[g * HH + (k - II)];
    }
    // layer2
    for (int idx = tid0; idx < 2 * K2 * 512; idx += stride) {
        int dir = idx / (K2 * 512);
        int r   = idx - dir * (K2 * 512);
        int k = r >> 9, g = r & 511;
        const float* wih = dir ? wih2b : wih2f;
        const float* whh = dir ? whh2b : whh2f;
        wt2[idx] = (k < 256) ? wih[g * 256 + k] : whh[g * HH + (k - 256)];
    }
    // biases
    for (int idx = tid0; idx < 512; idx += stride) {
        b1[idx]       = bih1f[idx] + bhh1f[idx];
        b1[idx + 512] = bih1b[idx] + bhh1b[idx];
        b2[idx]       = bih2f[idx] + bhh2f[idx];
        b2[idx + 512] = bih2b[idx] + bhh2b[idx];
    }
    // fc1 transpose
    for (int idx = tid0; idx < 512 * 64; idx += stride) {
        int j = idx / 512, k = idx % 512;
        fct[k * 64 + j] = fc1w[idx];
    }
}

// ---------------------------------------------------------------------------
// Fused LSTM layer kernel, SMEM-staged weights.
//  CTA = 64 batch x one direction, 512 threads.
//  SMEM: in_s [64][KTOT] ([x_t ; h]) + double-buffered weight chunk [2][CK][512].
//  Weights stream L2 -> SMEM once per CTA per step (cp.async, 1-deep pipeline).
//  Thread tile: 4 batch x 4 hidden-j x 4 gates, j paired for fma.rn.f32x2.
// ---------------------------------------------------------------------------
template<int IN, int KTOT>
__global__ __launch_bounds__(512, 1)
void lstm_kernel(const float* __restrict__ inp,   // [B][T][IN]
                 const float* __restrict__ wt,    // [2][KTOT][512]
                 const float* __restrict__ bias,  // [2][512]
                 float* __restrict__ outp)        // [B][T][256]
{
    constexpr int NC = KTOT / CK;                 // chunks per step
    extern __shared__ float smem[];
    float* in_s = smem;                           // [64][KTOT]
    float* wbuf = smem + 64 * KTOT;               // [2][CK][512]

    const int dir = blockIdx.y;
    const int b0  = blockIdx.x * 64;
    const float* W  = wt + (size_t)dir * KTOT * 512;
    const float* Bv = bias + dir * 512;

    const int tid = threadIdx.x;
    const int jq  = tid & 31;    // hidden quartet: j = jq*4 .. jq*4+3
    const int bq  = tid >> 5;    // batch quartet (warp id): b = bq*4 .. bq*4+3

    // zero h region of SMEM
    for (int idx = tid; idx < 64 * HH; idx += 512) {
        int b = idx >> 7;
        int k = idx & 127;
        in_s[b * KTOT + IN + k] = 0.0f;
    }
    __syncthreads();

    float cst[4][4];   // [j within quartet][batch within quartet]
#pragma unroll
    for (int a = 0; a < 4; a++)
#pragma unroll
        for (int b = 0; b < 4; b++) cst[a][b] = 0.0f;

    const float* xs = in_s + bq * 4 * KTOT;       // base for this thread's 4 rows

    for (int step = 0; step < TT; ++step) {
        const int t = dir ? (TT - 1 - step) : step;

        // stage x_t for this tile (coalesced; h region untouched)
        for (int idx = tid; idx < 64 * IN; idx += 512) {
            int b = idx / IN;
            int k = idx - b * IN;
            in_s[b * KTOT + k] = inp[((size_t)(b0 + b) * TT + t) * IN + k];
        }

        // prologue: load chunk 0 into buf 0 (buf0 free: prev step fully synced)
        {
            const float* src = W;                 // k rows [0, CK)
            float* dst = wbuf;
#pragma unroll
            for (int i = 0; i < CK * 512 / (512 * 4); i++)   // 6 x 16B per thread
                cp16(dst + (tid + i * 512) * 4, src + (tid + i * 512) * 4);
            cp_commit();
        }

        // accumulators: [gate][j-pair][batch], packed f32x2 over j
        ull acc[4][2][4];
#pragma unroll
        for (int g = 0; g < 4; g++) {
            float4 bv = *reinterpret_cast<const float4*>(Bv + g * 128 + jq * 4);
            ull p0 = pack2(bv.x, bv.y);
            ull p1 = pack2(bv.z, bv.w);
#pragma unroll
            for (int bb = 0; bb < 4; bb++) { acc[g][0][bb] = p0; acc[g][1][bb] = p1; }
        }

        for (int c = 0; c < NC; ++c) {
            cp_wait0();                 // chunk c landed
            __syncthreads();            // visible to all; prev chunk compute done

            if (c + 1 < NC) {           // prefetch chunk c+1 (overlaps compute c)
                const float* src = W + (size_t)(c + 1) * CK * 512;
                float* dst = wbuf + ((c + 1) & 1) * CK * 512;
#pragma unroll
                for (int i = 0; i < CK * 512 / (512 * 4); i++)
                    cp16(dst + (tid + i * 512) * 4, src + (tid + i * 512) * 4);
                cp_commit();
            }

            const float* wch = wbuf + (c & 1) * CK * 512 + jq * 4;
            const int kbase = c * CK;
#pragma unroll 2
            for (int kk = 0; kk < CK; ++kk) {
                ulonglong2 wv[4];
#pragma unroll
                for (int g = 0; g < 4; g++)
                    wv[g] = *reinterpret_cast<const ulonglong2*>(wch + kk * 512 + g * 128);

                const int k = kbase + kk;
                ull xp[4];
#pragma unroll
                for (int bb = 0; bb < 4; bb++) {
                    float xv = xs[bb * KTOT + k];
                    xp[bb] = pack2(xv, xv);
                }
#pragma unroll
                for (int g = 0; g < 4; g++) {
#pragma unroll
                    for (int bb = 0; bb < 4; bb++) {
                        acc[g][0][bb] = fma2(wv[g].x, xp[bb], acc[g][0][bb]);
                        acc[g][1][bb] = fma2(wv[g].y, xp[bb], acc[g][1][bb]);
                    }
                }
            }
        }

        __syncthreads();   // all reads of in_s done before h rewrite

        // activations + state update + h writeback
#pragma unroll
        for (int jp = 0; jp < 2; jp++) {
#pragma unroll
            for (int bb = 0; bb < 4; bb++) {
                float2 iv2 = unpack2(acc[0][jp][bb]);
                float2 fv2 = unpack2(acc[1][jp][bb]);
                float2 gv2 = unpack2(acc[2][jp][bb]);
                float2 ov2 = unpack2(acc[3][jp][bb]);
#pragma unroll
                for (int half = 0; half < 2; half++) {
                    float ig = half ? iv2.y : iv2.x;
                    float fg = half ? fv2.y : fv2.x;
                    float gg = half ? gv2.y : gv2.x;
                    float og = half ? ov2.y : ov2.x;
                    int jidx = jp * 2 + half;

                    float i_ = sigf(ig);
                    float f_ = sigf(fg);
                    float g_ = tanh_fast(gg);
                    float o_ = sigf(og);
                    float cc = f_ * cst[jidx][bb] + i_ * g_;
                    cst[jidx][bb] = cc;
                    float hv = o_ * tanh_fast(cc);

                    int j = jq * 4 + jidx;
                    int b = b0 + bq * 4 + bb;
                    in_s[(bq * 4 + bb) * KTOT + IN + j] = hv;
                    outp[((size_t)b * TT + t) * 256 + dir * HH + j] = hv;
                }
            }
        }
        __syncthreads();   // epilogue done before next step stages x / reuses buf0
    }
}

// ---------------------------------------------------------------------------
// Head: temporal max-pool (2 windows of 5) + fc1(512->64, relu) + fc2(64->1)
// ---------------------------------------------------------------------------
__global__ void head_kernel(const float* __restrict__ O2,
                            const float* __restrict__ fc1t,  // [k][64]
                            const float* __restrict__ fc1b,
                            const float* __restrict__ fc2w,
                            const float* __restrict__ fc2b,
                            float* __restrict__ out)
{
    __shared__ float pooled[4][512];
    __shared__ float red[4][2];

    const int tid = threadIdx.x;
    const int r   = tid >> 6;          // row within block (0..3)
    const int l   = tid & 63;          // lane within row
    const int b   = blockIdx.x * 4 + r;

#pragma unroll
    for (int ci = 0; ci < 4; ci++) {
        int c = l + ci * 64;           // channel 0..255
#pragma unroll
        for (int p = 0; p < 2; p++) {
            float m = -3.4e38f;
#pragma unroll
            for (int w = 0; w < 5; w++) {
                float v = O2[((size_t)b * TT + p * 5 + w) * 256 + c];
                m = fmaxf(m, v);
            }
            pooled[r][c * 2 + p] = m;
        }
    }
    __syncthreads();

    float s = fc1b[l];
    for (int k = 0; k < 512; k++)
        s += pooled[r][k] * fc1t[k * 64 + l];
    float v = fmaxf(s, 0.0f) * fc2w[l];

#pragma unroll
    for (int off = 16; off > 0; off >>= 1)
        v += __shfl_down_sync(0xffffffffu, v, off);
    if ((tid & 31) == 0) red[r][(tid >> 5) & 1] = v;
    __syncthreads();
    if (l == 0) out[b] = red[r][0] + red[r][1] + fc2b[0];
}

// ---------------------------------------------------------------------------
// Launch
// ---------------------------------------------------------------------------
extern "C" void kernel_launch(void* const* d_in, const int* in_sizes, int n_in,
                              void* d_out, int out_size)
{
    (void)in_sizes; (void)n_in; (void)out_size;
    const float* x       = (const float*)d_in[0];
    const float* fc1_b   = (const float*)d_in[18];
    const float* fc2_w   = (const float*)d_in[19];
    const float* fc2_b   = (const float*)d_in[20];
    float* out = (float*)d_out;

    float *WT1, *B1, *WT2, *B2, *O1, *O2, *FC1T;
    cudaGetSymbolAddress((void**)&WT1,  g_WT1);
    cudaGetSymbolAddress((void**)&B1,   g_B1);
    cudaGetSymbolAddress((void**)&WT2,  g_WT2);
    cudaGetSymbolAddress((void**)&B2,   g_B2);
    cudaGetSymbolAddress((void**)&O1,   g_O1);
    cudaGetSymbolAddress((void**)&O2,   g_O2);
    cudaGetSymbolAddress((void**)&FC1T, g_FC1T);

    // single fused prep launch (keeps ncu's -s window on the LSTM kernels)
    prep_all<<<296, 256>>>((const float*)d_in[1],  (const float*)d_in[2],
                           (const float*)d_in[3],  (const float*)d_in[4],
                           (const float*)d_in[5],  (const float*)d_in[6],
                           (const float*)d_in[7],  (const float*)d_in[8],
                           (const float*)d_in[9],  (const float*)d_in[10],
                           (const float*)d_in[11], (const float*)d_in[12],
                           (const float*)d_in[13], (const float*)d_in[14],
                           (const float*)d_in[15], (const float*)d_in[16],
                           (const float*)d_in[17],
                           WT1, B1, WT2, B2, FC1T);

    const int smem1 = (64 * K1 + 2 * CK * 512) * (int)sizeof(float);  // 178176
    const int smem2 = (64 * K2 + 2 * CK * 512) * (int)sizeof(float);  // 196608
    cudaFuncSetAttribute(lstm_kernel<II, K1>,
                         cudaFuncAttributeMaxDynamicSharedMemorySize, smem1);
    cudaFuncSetAttribute(lstm_kernel<256, K2>,
                         cudaFuncAttributeMaxDynamicSharedMemorySize, smem2);

    dim3 grid(BATCH / 64, 2);
    lstm_kernel<II, K1><<<grid, 512, smem1>>>(x,  WT1, B1, O1);
    lstm_kernel<256, K2><<<grid, 512, smem2>>>(O1, WT2, B2, O2);

    head_kernel<<<BATCH / 4, 256>>>(O2, FC1T, fc1_b, fc2_w, fc2_b, out);
}

// round 9
// speedup vs baseline: 1.8195x; 1.8195x over previous
#include <cuda_runtime.h>
#include <cuda_bf16.h>
#include <cstdint>

#define BATCH 16384
#define TT    10
#define HH    128

typedef unsigned int uint;
typedef unsigned short ushort;

// Layer geometry:
//  L1: INRAW=184 (fp32 x), INPAD=192, KPAD=320, KTILES=20, SA=328
//  L2: INRAW=256 (packed bf16 O1), INPAD=256, KPAD=384, KTILES=24, SA=392

// ---------------------------------------------------------------------------
// Scratch (device globals; no allocation allowed)
// ---------------------------------------------------------------------------
__device__ uint4 g_Wf1[2 * 20 * 2048];   // [dir][k16][ntile(64)][lane(32)] frag-packed
__device__ uint4 g_Wf2[2 * 24 * 2048];
__device__ float g_Bc1[2 * 512];         // bias, gate-interleaved col order c = 4j+g
__device__ float g_Bc2[2 * 512];
__device__ uint  g_O1 [(size_t)BATCH * TT * 256];  // layer1 out: (bf16 hi <<16)|lo
__device__ float g_O2 [(size_t)BATCH * TT * 256];  // layer2 out fp32
__device__ float g_FC1T[512 * 64];       // fc1_w transposed [k][j]

// ---------------------------------------------------------------------------
// bf16 split helpers
// ---------------------------------------------------------------------------
__device__ __forceinline__ ushort bfb(float x) {
    __nv_bfloat16 b = __float2bfloat16(x);
    return *reinterpret_cast<ushort*>(&b);
}
__device__ __forceinline__ float bff(ushort u) {
    __nv_bfloat16 b; *reinterpret_cast<ushort*>(&b) = u;
    return __bfloat162float(b);
}

// ---------------------------------------------------------------------------
// MUFU-free activations (FMA/ALU only)
// ---------------------------------------------------------------------------
__device__ __forceinline__ float exp2m(float t) {          // 2^t
    t = fminf(fmaxf(t, -60.0f), 60.0f);
    float fi = t + 12582912.0f;                            // round to nearest int
    int   ii = __float_as_int(fi) - 0x4B400000;
    float f  = t - (fi - 12582912.0f);                     // frac in [-0.5, 0.5]
    float p  =            1.5403530e-4f;
    p = fmaf(p, f, 1.3333558e-3f);
    p = fmaf(p, f, 9.6181291e-3f);
    p = fmaf(p, f, 5.5504109e-2f);
    p = fmaf(p, f, 2.4022651e-1f);
    p = fmaf(p, f, 6.9314718e-1f);
    p = fmaf(p, f, 1.0f);
    return __int_as_float(__float_as_int(p) + (ii << 23));
}
__device__ __forceinline__ float rcp_fast(float d) {       // 1/d, d > 0
    float y = __int_as_float(0x7EF311C3 - __float_as_int(d));
    y = y * (2.0f - d * y);
    y = y * (2.0f - d * y);
    y = y * (2.0f - d * y);
    return y;
}
__device__ __forceinline__ float sigp(float x) {
    return rcp_fast(1.0f + exp2m(-1.4426950408889634f * x));
}
__device__ __forceinline__ float tanhp(float x) {
    return fmaf(2.0f, rcp_fast(1.0f + exp2m(-2.8853900817779268f * x)), -1.0f);
}

// ---------------------------------------------------------------------------
// MMA / ldmatrix / cp.async
// ---------------------------------------------------------------------------
__device__ __forceinline__ void mma16816(float* d, const uint* a, uint b0, uint b1) {
    asm volatile("mma.sync.aligned.m16n8k16.row.col.f32.bf16.bf16.f32 "
        "{%0,%1,%2,%3},{%4,%5,%6,%7},{%8,%9},{%0,%1,%2,%3};"
        : "+f"(d[0]), "+f"(d[1]), "+f"(d[2]), "+f"(d[3])
        : "r"(a[0]), "r"(a[1]), "r"(a[2]), "r"(a[3]), "r"(b0), "r"(b1));
}
__device__ __forceinline__ void ldmA(uint* a, const ushort* p) {
    uint addr = (uint)__cvta_generic_to_shared(p);
    asm volatile("ldmatrix.sync.aligned.m8n8.x4.shared.b16 {%0,%1,%2,%3}, [%4];"
        : "=r"(a[0]), "=r"(a[1]), "=r"(a[2]), "=r"(a[3]) : "r"(addr));
}
__device__ __forceinline__ void cp16(void* dst, const void* src) {
    unsigned s = (unsigned)__cvta_generic_to_shared(dst);
    asm volatile("cp.async.cg.shared.global [%0], [%1], 16;" :: "r"(s), "l"(src));
}
__device__ __forceinline__ void cp_commit() { asm volatile("cp.async.commit_group;"); }
__device__ __forceinline__ void cp_wait0()  { asm volatile("cp.async.wait_group 0;" ::: "memory"); }

// ---------------------------------------------------------------------------
// Prep: fragment-pack weights (hi/lo split, gate-interleaved cols), biases, fc1T
// ---------------------------------------------------------------------------
__device__ void pack_layer(int tid0, int stride,
                           const float* wihf, const float* whhf,
                           const float* wihb, const float* whhb,
                           int IN, int INPAD, int KT, uint4* wf)
{
    const int total = 2 * KT * 2048;
    for (int idx = tid0; idx < total; idx += stride) {
        int dir = idx / (KT * 2048);
        int rem = idx - dir * (KT * 2048);
        int q    = rem & 2047;
        int k16  = rem >> 11;
        int nt   = q >> 5, lane = q & 31;
        int n    = nt * 8 + (lane >> 2);          // global col c
        int ka   = k16 * 16 + (lane & 3) * 2;
        int G    = (n & 3) * 128 + (n >> 2);      // c = 4j+g -> gate-major row
        const float* wih = dir ? wihb : wihf;
        const float* whh = dir ? whhb : whhf;
        int ks[4] = {ka, ka + 1, ka + 8, ka + 9};
        ushort h[4], l[4];
#pragma unroll
        for (int i = 0; i < 4; i++) {
            int k = ks[i];
            float v = (k < IN) ? wih[G * IN + k]
                    : (k < INPAD ? 0.0f : whh[G * HH + (k - INPAD)]);
            h[i] = bfb(v);
            l[i] = bfb(v - bff(h[i]));
        }
        uint4 r;
        r.x = (uint)h[0] | ((uint)h[1] << 16);
        r.y = (uint)h[2] | ((uint)h[3] << 16);
        r.z = (uint)l[0] | ((uint)l[1] << 16);
        r.w = (uint)l[2] | ((uint)l[3] << 16);
        wf[idx] = r;
    }
}

__global__ void prep_all(const float* wih1f, const float* whh1f,
                         const float* bih1f, const float* bhh1f,
                         const float* wih1b, const float* whh1b,
                         const float* bih1b, const float* bhh1b,
                         const float* wih2f, const float* whh2f,
                         const float* bih2f, const float* bhh2f,
                         const float* wih2b, const float* whh2b,
                         const float* bih2b, const float* bhh2b,
                         const float* fc1w,
                         uint4* wf1, float* bc1, uint4* wf2, float* bc2,
                         float* fct)
{
    const int stride = gridDim.x * blockDim.x;
    const int tid0 = blockIdx.x * blockDim.x + threadIdx.x;

    pack_layer(tid0, stride, wih1f, whh1f, wih1b, whh1b, 184, 192, 20, wf1);
    pack_layer(tid0, stride, wih2f, whh2f, wih2b, whh2b, 256, 256, 24, wf2);

    for (int idx = tid0; idx < 2 * 512; idx += stride) {
        int dir = idx >> 9, c = idx & 511;
        int G = (c & 3) * 128 + (c >> 2);
        bc1[idx] = (dir ? bih1b : bih1f)[G] + (dir ? bhh1b : bhh1f)[G];
        bc2[idx] = (dir ? bih2b : bih2f)[G] + (dir ? bhh2b : bhh2f)[G];
    }
    for (int idx = tid0; idx < 512 * 64; idx += stride) {
        int j = idx / 512, k = idx % 512;
        fct[k * 64 + j] = fc1w[idx];
    }
}

// ---------------------------------------------------------------------------
// Fused LSTM layer, tensor-core GEMM (3x bf16-split), persistent c-state.
//  CTA = 64 batch x one direction, 512 threads = 16 warps.
//  Warp w: m-tile wm = w>>2 (16 rows), n-block wn = w&3 (16 n-tiles = 128 cols).
// ---------------------------------------------------------------------------
template<int INRAW, int INPAD, int KTILES, int IS_L1>
__global__ __launch_bounds__(512, 1)
void lstm_mma(const void* __restrict__ inp_,
              const uint4* __restrict__ wf,
              const float* __restrict__ bc,
              void* __restrict__ outp_)
{
    constexpr int KPAD = INPAD + HH;
    constexpr int SA   = KPAD + 8;           // row stride (2*SA bytes ≡ 4 banks mod 32)
    extern __shared__ char smem_raw[];
    ushort* A_hi = (ushort*)smem_raw;                 // [64][SA]
    ushort* A_lo = A_hi + 64 * SA;
    uint4*  wbuf = (uint4*)(A_lo + 64 * SA);          // [2][2048]
    float*  bias_s = (float*)(wbuf + 2 * 2048);       // [512]

    const int dir = blockIdx.y;
    const int b0  = blockIdx.x * 64;
    const uint4* W = wf + (size_t)dir * KTILES * 2048;

    const int tid  = threadIdx.x;
    const int lane = tid & 31;
    const int w    = tid >> 5;
    const int wm   = w >> 2;
    const int wn   = w & 3;

    bias_s[tid & 511] = bc[dir * 512 + (tid & 511)];

    // zero pad + initial-h region (cols [INRAW, SA)) — h=0 at t=0
    for (int idx = tid; idx < 64 * (SA - INRAW); idx += 512) {
        int r = idx / (SA - INRAW);
        int k = INRAW + idx % (SA - INRAW);
        A_hi[r * SA + k] = 0;
        A_lo[r * SA + k] = 0;
    }
    __syncthreads();

    float cst[16];
#pragma unroll
    for (int i = 0; i < 16; i++) cst[i] = 0.0f;

    // epilogue cell coordinates (fixed per thread)
    const int row_loc = wm * 16 + (lane >> 2) + ((lane & 1) << 3);
    const int jsub    = (lane >> 1) & 1;

    // ldmatrix per-lane address base
    const int lrow = wm * 16 + (lane & 15);
    const int lcol = (lane & 16) ? 8 : 0;
    const ushort* pAh = A_hi + lrow * SA + lcol;
    const ushort* pAl = A_lo + lrow * SA + lcol;

    for (int step = 0; step < TT; ++step) {
        const int t = dir ? (TT - 1 - step) : step;

        // ---- stage inputs into A_s x-region ----
        if (IS_L1) {
            const float* x = (const float*)inp_;
            for (int idx = tid; idx < 64 * INRAW; idx += 512) {
                int b = idx / INRAW, k = idx - b * INRAW;
                float v = x[((size_t)(b0 + b) * TT + t) * INRAW + k];
                ushort hb = bfb(v);
                A_hi[b * SA + k] = hb;
                A_lo[b * SA + k] = bfb(v - bff(hb));
            }
        } else {
            const uint* xin = (const uint*)inp_;
            for (int idx = tid; idx < 64 * 256; idx += 512) {
                int b = idx >> 8, k = idx & 255;
                uint u = xin[((size_t)(b0 + b) * TT + t) * 256 + k];
                A_hi[b * SA + k] = (ushort)(u >> 16);
                A_lo[b * SA + k] = (ushort)(u & 0xffff);
            }
        }

        // ---- prologue: weight chunk 0 -> buf 0 ----
        {
            const uint4* src = W;
            uint4* dst = wbuf;
#pragma unroll
            for (int i = 0; i < 4; i++) cp16(dst + tid * 4 + i, src + tid * 4 + i);
            cp_commit();
        }

        // ---- acc init from gate-interleaved bias ----
        float acc[16][4];
#pragma unroll
        for (int nt = 0; nt < 16; nt++) {
            int c0 = wn * 128 + nt * 8 + (lane & 3) * 2;
            float2 bb = *(const float2*)(bias_s + c0);
            acc[nt][0] = bb.x; acc[nt][1] = bb.y;
            acc[nt][2] = bb.x; acc[nt][3] = bb.y;
        }

        // ---- k16-tile loop ----
        for (int c = 0; c < KTILES; ++c) {
            cp_wait0();
            __syncthreads();
            if (c + 1 < KTILES) {
                const uint4* src = W + (size_t)(c + 1) * 2048;
                uint4* dst = wbuf + ((c + 1) & 1) * 2048;
#pragma unroll
                for (int i = 0; i < 4; i++) cp16(dst + tid * 4 + i, src + tid * 4 + i);
                cp_commit();
            }
            uint ah[4], al[4];
            ldmA(ah, pAh + c * 16);
            ldmA(al, pAl + c * 16);
            const uint4* wb = wbuf + (c & 1) * 2048 + (wn * 16) * 32 + lane;
#pragma unroll
            for (int nt = 0; nt < 16; nt++) {
                uint4 b = wb[nt * 32];
                mma16816(acc[nt], ah, b.x, b.y);   // hiA * hiB
                mma16816(acc[nt], al, b.x, b.y);   // loA * hiB
                mma16816(acc[nt], ah, b.z, b.w);   // hiA * loB
            }
        }
        __syncthreads();   // all mma reads of A_s done before h rewrite

        // ---- epilogue: gate exchange + cell update + h writeback ----
#pragma unroll
        for (int nt = 0; nt < 16; nt++) {
            float t0 = __shfl_xor_sync(0xffffffffu, acc[nt][0], 1);
            float t1 = __shfl_xor_sync(0xffffffffu, acc[nt][1], 1);
            float t2 = __shfl_xor_sync(0xffffffffu, acc[nt][2], 1);
            float t3 = __shfl_xor_sync(0xffffffffu, acc[nt][3], 1);
            float gi, gf, gg, go;
            if ((lane & 1) == 0) { gi = acc[nt][0]; gf = acc[nt][1]; gg = t0; go = t1; }
            else                 { gi = t2;         gf = t3;         gg = acc[nt][2]; go = acc[nt][3]; }

            float cc = sigp(gf) * cst[nt] + sigp(gi) * tanhp(gg);
            cst[nt] = cc;
            float hv = sigp(go) * tanhp(cc);

            int j = wn * 32 + nt * 2 + jsub;
            ushort hb = bfb(hv);
            ushort lb = bfb(hv - bff(hb));
            A_hi[row_loc * SA + INPAD + j] = hb;
            A_lo[row_loc * SA + INPAD + j] = lb;

            size_t oidx = ((size_t)(b0 + row_loc) * TT + t) * 256 + dir * HH + j;
            if (IS_L1) ((uint*)outp_)[oidx] = ((uint)hb << 16) | (uint)lb;
            else       ((float*)outp_)[oidx] = hv;
        }
        // next step's first in-loop __syncthreads orders h-writes vs mma reads
    }
}

// ---------------------------------------------------------------------------
// Head: temporal max-pool (2 windows of 5) + fc1(512->64, relu) + fc2(64->1)
// ---------------------------------------------------------------------------
__global__ void head_kernel(const float* __restrict__ O2,
                            const float* __restrict__ fc1t,  // [k][64]
                            const float* __restrict__ fc1b,
                            const float* __restrict__ fc2w,
                            const float* __restrict__ fc2b,
                            float* __restrict__ out)
{
    __shared__ float pooled[4][512];
    __shared__ float red[4][2];

    const int tid = threadIdx.x;
    const int r   = tid >> 6;
    const int l   = tid & 63;
    const int b   = blockIdx.x * 4 + r;

#pragma unroll
    for (int ci = 0; ci < 4; ci++) {
        int c = l + ci * 64;
#pragma unroll
        for (int p = 0; p < 2; p++) {
            float m = -3.4e38f;
#pragma unroll
            for (int w = 0; w < 5; w++) {
                float v = O2[((size_t)b * TT + p * 5 + w) * 256 + c];
                m = fmaxf(m, v);
            }
            pooled[r][c * 2 + p] = m;
        }
    }
    __syncthreads();

    float s = fc1b[l];
    for (int k = 0; k < 512; k++)
        s += pooled[r][k] * fc1t[k * 64 + l];
    float v = fmaxf(s, 0.0f) * fc2w[l];

#pragma unroll
    for (int off = 16; off > 0; off >>= 1)
        v += __shfl_down_sync(0xffffffffu, v, off);
    if ((tid & 31) == 0) red[r][(tid >> 5) & 1] = v;
    __syncthreads();
    if (l == 0) out[b] = red[r][0] + red[r][1] + fc2b[0];
}

// ---------------------------------------------------------------------------
// Launch
// ---------------------------------------------------------------------------
extern "C" void kernel_launch(void* const* d_in, const int* in_sizes, int n_in,
                              void* d_out, int out_size)
{
    (void)in_sizes; (void)n_in; (void)out_size;
    const float* x     = (const float*)d_in[0];
    const float* fc1_b = (const float*)d_in[18];
    const float* fc2_w = (const float*)d_in[19];
    const float* fc2_b = (const float*)d_in[20];
    float* out = (float*)d_out;

    uint4 *WF1, *WF2;
    float *BC1, *BC2, *O2, *FC1T;
    uint  *O1;
    cudaGetSymbolAddress((void**)&WF1,  g_Wf1);
    cudaGetSymbolAddress((void**)&WF2,  g_Wf2);
    cudaGetSymbolAddress((void**)&BC1,  g_Bc1);
    cudaGetSymbolAddress((void**)&BC2,  g_Bc2);
    cudaGetSymbolAddress((void**)&O1,   g_O1);
    cudaGetSymbolAddress((void**)&O2,   g_O2);
    cudaGetSymbolAddress((void**)&FC1T, g_FC1T);

    prep_all<<<296, 256>>>((const float*)d_in[1],  (const float*)d_in[2],
                           (const float*)d_in[3],  (const float*)d_in[4],
                           (const float*)d_in[5],  (const float*)d_in[6],
                           (const float*)d_in[7],  (const float*)d_in[8],
                           (const float*)d_in[9],  (const float*)d_in[10],
                           (const float*)d_in[11], (const float*)d_in[12],
                           (const float*)d_in[13], (const float*)d_in[14],
                           (const float*)d_in[15], (const float*)d_in[16],
                           (const float*)d_in[17],
                           WF1, BC1, WF2, BC2, FC1T);

    // SMEM: A_hi + A_lo + 2x32KB weight ring + 512-float bias
    const int smem1 = 64 * 328 * 2 * 2 + 2 * 2048 * 16 + 512 * 4;  // 151,552
    const int smem2 = 64 * 392 * 2 * 2 + 2 * 2048 * 16 + 512 * 4;  // 167,936
    cudaFuncSetAttribute(lstm_mma<184, 192, 20, 1>,
                         cudaFuncAttributeMaxDynamicSharedMemorySize, smem1);
    cudaFuncSetAttribute(lstm_mma<256, 256, 24, 0>,
                         cudaFuncAttributeMaxDynamicSharedMemorySize, smem2);

    dim3 grid(BATCH / 64, 2);
    lstm_mma<184, 192, 20, 1><<<grid, 512, smem1>>>(x,  WF1, BC1, O1);
    lstm_mma<256, 256, 24, 0><<<grid, 512, smem2>>>(O1, WF2, BC2, O2);

    head_kernel<<<BATCH / 4, 256>>>(O2, FC1T, fc1_b, fc2_w, fc2_b, out);
}

// round 13
// speedup vs baseline: 2.0364x; 1.1192x over previous
#include <cuda_runtime.h>
#include <cuda_bf16.h>
#include <cstdint>

#define BATCH 16384
#define TT    10
#define HH    128

typedef unsigned int uint;
typedef unsigned short ushort;

// Layer geometry:
//  L1: INRAW=184 (fp32 x), INPAD=192, KPAD=320, KTILES=20, SA=328
//  L2: INRAW=256 (packed bf16 O1), INPAD=256, KPAD=384, KTILES=24, SA=392

// ---------------------------------------------------------------------------
// Scratch (device globals; no allocation allowed)
// ---------------------------------------------------------------------------
__device__ uint4 g_Wf1[2 * 20 * 2048];   // [dir][k16][ntile(64)][lane(32)] frag-packed
__device__ uint4 g_Wf2[2 * 24 * 2048];
__device__ float g_Bc1[2 * 512];         // bias, gate-interleaved col order c = 4j+g
__device__ float g_Bc2[2 * 512];
__device__ uint  g_O1 [(size_t)BATCH * TT * 256];  // layer1 out: (bf16 hi <<16)|lo
__device__ float g_O2 [(size_t)BATCH * TT * 256];  // layer2 out fp32
__device__ float g_FC1T[512 * 64];       // fc1_w transposed [k][j]

// ---------------------------------------------------------------------------
// bf16 split helpers
// ---------------------------------------------------------------------------
__device__ __forceinline__ ushort bfb(float x) {
    __nv_bfloat16 b = __float2bfloat16(x);
    return *reinterpret_cast<ushort*>(&b);
}
__device__ __forceinline__ float bff(ushort u) {
    __nv_bfloat16 b; *reinterpret_cast<ushort*>(&b) = u;
    return __bfloat162float(b);
}

// ---------------------------------------------------------------------------
// MUFU-free activations (FMA/ALU only)
// ---------------------------------------------------------------------------
__device__ __forceinline__ float exp2m(float t) {          // 2^t
    t = fminf(fmaxf(t, -60.0f), 60.0f);
    float fi = t + 12582912.0f;                            // round to nearest int
    int   ii = __float_as_int(fi) - 0x4B400000;
    float f  = t - (fi - 12582912.0f);                     // frac in [-0.5, 0.5]
    float p  =            1.5403530e-4f;
    p = fmaf(p, f, 1.3333558e-3f);
    p = fmaf(p, f, 9.6181291e-3f);
    p = fmaf(p, f, 5.5504109e-2f);
    p = fmaf(p, f, 2.4022651e-1f);
    p = fmaf(p, f, 6.9314718e-1f);
    p = fmaf(p, f, 1.0f);
    return __int_as_float(__float_as_int(p) + (ii << 23));
}
__device__ __forceinline__ float rcp_fast(float d) {       // 1/d, d > 0
    float y = __int_as_float(0x7EF311C3 - __float_as_int(d));
    y = y * (2.0f - d * y);
    y = y * (2.0f - d * y);
    y = y * (2.0f - d * y);
    return y;
}
__device__ __forceinline__ float sigp(float x) {
    return rcp_fast(1.0f + exp2m(-1.4426950408889634f * x));
}
__device__ __forceinline__ float tanhp(float x) {
    return fmaf(2.0f, rcp_fast(1.0f + exp2m(-2.8853900817779268f * x)), -1.0f);
}

// ---------------------------------------------------------------------------
// MMA / ldmatrix / TMA bulk copy / mbarrier
// ---------------------------------------------------------------------------
__device__ __forceinline__ void mma16816(float* d, const uint* a, uint b0, uint b1) {
    asm volatile("mma.sync.aligned.m16n8k16.row.col.f32.bf16.bf16.f32 "
        "{%0,%1,%2,%3},{%4,%5,%6,%7},{%8,%9},{%0,%1,%2,%3};"
        : "+f"(d[0]), "+f"(d[1]), "+f"(d[2]), "+f"(d[3])
        : "r"(a[0]), "r"(a[1]), "r"(a[2]), "r"(a[3]), "r"(b0), "r"(b1));
}
__device__ __forceinline__ void ldmA(uint* a, const ushort* p) {
    uint addr = (uint)__cvta_generic_to_shared(p);
    asm volatile("ldmatrix.sync.aligned.m8n8.x4.shared.b16 {%0,%1,%2,%3}, [%4];"
        : "=r"(a[0]), "=r"(a[1]), "=r"(a[2]), "=r"(a[3]) : "r"(addr));
}
__device__ __forceinline__ void bulk_cp(void* dst_smem, const void* src,
                                        uint bytes, uint mbar) {
    uint d = (uint)__cvta_generic_to_shared(dst_smem);
    asm volatile("cp.async.bulk.shared::cta.global.mbarrier::complete_tx::bytes "
                 "[%0], [%1], %2, [%3];"
                 :: "r"(d), "l"(src), "r"(bytes), "r"(mbar) : "memory");
}
__device__ __forceinline__ void mbar_init(uint mbar, uint cnt) {
    asm volatile("mbarrier.init.shared.b64 [%0], %1;" :: "r"(mbar), "r"(cnt) : "memory");
}
__device__ __forceinline__ void mbar_expect(uint mbar, uint bytes) {
    asm volatile("mbarrier.arrive.expect_tx.shared.b64 _, [%0], %1;"
                 :: "r"(mbar), "r"(bytes) : "memory");
}
__device__ __forceinline__ void mbar_wait(uint mbar, uint parity) {
    asm volatile(
        "{\n\t.reg .pred P1;\n\t"
        "WAIT_%=:\n\t"
        "mbarrier.try_wait.parity.acquire.cta.shared::cta.b64 P1, [%0], %1, 0x989680;\n\t"
        "@P1 bra DONE_%=;\n\t"
        "bra WAIT_%=;\n\t"
        "DONE_%=:\n\t}"
        :: "r"(mbar), "r"(parity) : "memory");
}

// ---------------------------------------------------------------------------
// Prep: fragment-pack weights (hi/lo split, gate-interleaved cols), biases, fc1T
// ---------------------------------------------------------------------------
__device__ void pack_layer(int tid0, int stride,
                           const float* wihf, const float* whhf,
                           const float* wihb, const float* whhb,
                           int IN, int INPAD, int KT, uint4* wf)
{
    const int total = 2 * KT * 2048;
    for (int idx = tid0; idx < total; idx += stride) {
        int dir = idx / (KT * 2048);
        int rem = idx - dir * (KT * 2048);
        int q    = rem & 2047;
        int k16  = rem >> 11;
        int nt   = q >> 5, lane = q & 31;
        int n    = nt * 8 + (lane >> 2);          // global col c
        int ka   = k16 * 16 + (lane & 3) * 2;
        int G    = (n & 3) * 128 + (n >> 2);      // c = 4j+g -> gate-major row
        const float* wih = dir ? wihb : wihf;
        const float* whh = dir ? whhb : whhf;
        int ks[4] = {ka, ka + 1, ka + 8, ka + 9};
        ushort h[4], l[4];
#pragma unroll
        for (int i = 0; i < 4; i++) {
            int k = ks[i];
            float v = (k < IN) ? wih[G * IN + k]
                    : (k < INPAD ? 0.0f : whh[G * HH + (k - INPAD)]);
            h[i] = bfb(v);
            l[i] = bfb(v - bff(h[i]));
        }
        uint4 r;
        r.x = (uint)h[0] | ((uint)h[1] << 16);
        r.y = (uint)h[2] | ((uint)h[3] << 16);
        r.z = (uint)l[0] | ((uint)l[1] << 16);
        r.w = (uint)l[2] | ((uint)l[3] << 16);
        wf[idx] = r;
    }
}

__global__ void prep_all(const float* wih1f, const float* whh1f,
                         const float* bih1f, const float* bhh1f,
                         const float* wih1b, const float* whh1b,
                         const float* bih1b, const float* bhh1b,
                         const float* wih2f, const float* whh2f,
                         const float* bih2f, const float* bhh2f,
                         const float* wih2b, const float* whh2b,
                         const float* bih2b, const float* bhh2b,
                         const float* fc1w,
                         uint4* wf1, float* bc1, uint4* wf2, float* bc2,
                         float* fct)
{
    const int stride = gridDim.x * blockDim.x;
    const int tid0 = blockIdx.x * blockDim.x + threadIdx.x;

    pack_layer(tid0, stride, wih1f, whh1f, wih1b, whh1b, 184, 192, 20, wf1);
    pack_layer(tid0, stride, wih2f, whh2f, wih2b, whh2b, 256, 256, 24, wf2);

    for (int idx = tid0; idx < 2 * 512; idx += stride) {
        int dir = idx >> 9, c = idx & 511;
        int G = (c & 3) * 128 + (c >> 2);
        bc1[idx] = (dir ? bih1b : bih1f)[G] + (dir ? bhh1b : bhh1f)[G];
        bc2[idx] = (dir ? bih2b : bih2f)[G] + (dir ? bhh2b : bhh2f)[G];
    }
    for (int idx = tid0; idx < 512 * 64; idx += stride) {
        int j = idx / 512, k = idx % 512;
        fct[k * 64 + j] = fc1w[idx];
    }
}

// ---------------------------------------------------------------------------
// Fused LSTM layer, tensor-core GEMM (3x bf16-split), persistent c-state.
//  Weights stream L2 -> SMEM as ONE 32KB cp.async.bulk per k16-tile
//  (double-buffered, mbarrier completion) — removes the LDGSTS issue bound.
// ---------------------------------------------------------------------------
template<int INRAW, int INPAD, int KTILES, int IS_L1>
__global__ __launch_bounds__(512, 1)
void lstm_mma(const void* __restrict__ inp_,
              const uint4* __restrict__ wf,
              const float* __restrict__ bc,
              void* __restrict__ outp_)
{
    constexpr int KPAD = INPAD + HH;
    constexpr int SA   = KPAD + 8;           // row stride (2*SA bytes ≡ 4 banks mod 32)
    extern __shared__ char smem_raw[];
    ushort* A_hi = (ushort*)smem_raw;                 // [64][SA]
    ushort* A_lo = A_hi + 64 * SA;
    uint4*  wbuf = (uint4*)(A_lo + 64 * SA);          // [2][2048] (2 x 32KB)
    float*  bias_s = (float*)(wbuf + 2 * 2048);       // [512]
    uint    mbar0 = (uint)__cvta_generic_to_shared(bias_s + 512);   // 2 x 8B
    uint    mbar1 = mbar0 + 8;

    const int dir = blockIdx.y;
    const int b0  = blockIdx.x * 64;
    const uint4* W = wf + (size_t)dir * KTILES * 2048;

    const int tid  = threadIdx.x;
    const int lane = tid & 31;
    const int w    = tid >> 5;
    const int wm   = w >> 2;
    const int wn   = w & 3;

    bias_s[tid & 511] = bc[dir * 512 + (tid & 511)];
    if (tid == 0) { mbar_init(mbar0, 1); mbar_init(mbar1, 1); }

    // zero pad + initial-h region (cols [INRAW, SA)) — h=0 at t=0
    for (int idx = tid; idx < 64 * (SA - INRAW); idx += 512) {
        int r = idx / (SA - INRAW);
        int k = INRAW + idx % (SA - INRAW);
        A_hi[r * SA + k] = 0;
        A_lo[r * SA + k] = 0;
    }
    __syncthreads();

    float cst[16];
#pragma unroll
    for (int i = 0; i < 16; i++) cst[i] = 0.0f;

    uint ph0 = 0, ph1 = 0;   // per-buffer mbarrier phase (per-thread, identical)

    // epilogue cell coordinates (fixed per thread)
    const int row_loc = wm * 16 + (lane >> 2) + ((lane & 1) << 3);
    const int jsub    = (lane >> 1) & 1;

    // ldmatrix per-lane address base
    const int lrow = wm * 16 + (lane & 15);
    const int lcol = (lane & 16) ? 8 : 0;
    const ushort* pAh = A_hi + lrow * SA + lcol;
    const ushort* pAl = A_lo + lrow * SA + lcol;

    for (int step = 0; step < TT; ++step) {
        const int t = dir ? (TT - 1 - step) : step;

        // ---- issue weight chunk 0 -> buf 0 (safe: compute of last even chunk
        //      of prev step finished before prev step's final k-loop barrier) ----
        if (tid == 0) {
            mbar_expect(mbar0, 32768);
            bulk_cp(wbuf, W, 32768, mbar0);
        }

        // ---- stage inputs into A_s x-region ----
        if (IS_L1) {
            const float* x = (const float*)inp_;
            for (int idx = tid; idx < 64 * INRAW; idx += 512) {
                int b = idx / INRAW, k = idx - b * INRAW;
                float v = x[((size_t)(b0 + b) * TT + t) * INRAW + k];
                ushort hb = bfb(v);
                A_hi[b * SA + k] = hb;
                A_lo[b * SA + k] = bfb(v - bff(hb));
            }
        } else {
            const uint* xin = (const uint*)inp_;
            for (int idx = tid; idx < 64 * 256; idx += 512) {
                int b = idx >> 8, k = idx & 255;
                uint u = xin[((size_t)(b0 + b) * TT + t) * 256 + k];
                A_hi[b * SA + k] = (ushort)(u >> 16);
                A_lo[b * SA + k] = (ushort)(u & 0xffff);
            }
        }

        // ---- acc init from gate-interleaved bias ----
        float acc[16][4];
#pragma unroll
        for (int nt = 0; nt < 16; nt++) {
            int c0 = wn * 128 + nt * 8 + (lane & 3) * 2;
            float2 bb = *(const float2*)(bias_s + c0);
            acc[nt][0] = bb.x; acc[nt][1] = bb.y;
            acc[nt][2] = bb.x; acc[nt][3] = bb.y;
        }

        // ---- k16-tile loop ----
        for (int c = 0; c < KTILES; ++c) {
            if (c & 1) { mbar_wait(mbar1, ph1); ph1 ^= 1; }
            else       { mbar_wait(mbar0, ph0); ph0 ^= 1; }
            __syncthreads();            // all threads past wait; compute c-1 done
            if (c + 1 < KTILES && tid == 0) {
                uint mb = ((c + 1) & 1) ? mbar1 : mbar0;
                mbar_expect(mb, 32768);
                bulk_cp(wbuf + ((c + 1) & 1) * 2048,
                        W + (size_t)(c + 1) * 2048, 32768, mb);
            }
            uint ah[4], al[4];
            ldmA(ah, pAh + c * 16);
            ldmA(al, pAl + c * 16);
            const uint4* wb = wbuf + (c & 1) * 2048 + (wn * 16) * 32 + lane;
#pragma unroll
            for (int nt = 0; nt < 16; nt++) {
                uint4 b = wb[nt * 32];
                mma16816(acc[nt], ah, b.x, b.y);   // hiA * hiB
                mma16816(acc[nt], al, b.x, b.y);   // loA * hiB
                mma16816(acc[nt], ah, b.z, b.w);   // hiA * loB
            }
        }
        __syncthreads();   // all mma reads of A_s done before h rewrite

        // ---- epilogue: gate exchange + cell update + h writeback ----
#pragma unroll
        for (int nt = 0; nt < 16; nt++) {
            float t0 = __shfl_xor_sync(0xffffffffu, acc[nt][0], 1);
            float t1 = __shfl_xor_sync(0xffffffffu, acc[nt][1], 1);
            float t2 = __shfl_xor_sync(0xffffffffu, acc[nt][2], 1);
            float t3 = __shfl_xor_sync(0xffffffffu, acc[nt][3], 1);
            float gi, gf, gg, go;
            if ((lane & 1) == 0) { gi = acc[nt][0]; gf = acc[nt][1]; gg = t0; go = t1; }
            else                 { gi = t2;         gf = t3;         gg = acc[nt][2]; go = acc[nt][3]; }

            float cc = sigp(gf) * cst[nt] + sigp(gi) * tanhp(gg);
            cst[nt] = cc;
            float hv = sigp(go) * tanhp(cc);

            int j = wn * 32 + nt * 2 + jsub;
            ushort hb = bfb(hv);
            ushort lb = bfb(hv - bff(hb));
            A_hi[row_loc * SA + INPAD + j] = hb;
            A_lo[row_loc * SA + INPAD + j] = lb;

            size_t oidx = ((size_t)(b0 + row_loc) * TT + t) * 256 + dir * HH + j;
            if (IS_L1) ((uint*)outp_)[oidx] = ((uint)hb << 16) | (uint)lb;
            else       ((float*)outp_)[oidx] = hv;
        }
        // next step's first in-loop __syncthreads orders h-writes vs mma reads
    }
}

// ---------------------------------------------------------------------------
// Head: 32 rows / 512-thread block; fc1t staged in SMEM once per block.
// pooled flat index = channel*2 + window  (matches transpose(0,2,1).reshape)
// ---------------------------------------------------------------------------
#define HROWS 32
#define PSTR  516   // pooled row stride (floats): breaks bank alignment

__global__ __launch_bounds__(512, 1)
void head_kernel(const float* __restrict__ O2,
                 const float* __restrict__ fc1t,  // [k][64]
                 const float* __restrict__ fc1b,
                 const float* __restrict__ fc2w,
                 const float* __restrict__ fc2b,
                 float* __restrict__ out)
{
    extern __shared__ float hs[];
    float* fc1t_s = hs;                  // [512][64]
    float* pooled = hs + 512 * 64;       // [HROWS][PSTR]

    const int tid = threadIdx.x;
    const int b0  = blockIdx.x * HROWS;

    for (int i = tid; i < 512 * 64; i += 512) fc1t_s[i] = fc1t[i];

    // pooling: HROWS x 256 channels, 2 windows of 5
    for (int it = tid; it < HROWS * 256; it += 512) {
        int r = it >> 8, c = it & 255;
        const float* p = O2 + ((size_t)(b0 + r) * TT) * 256 + c;
        float m0 = p[0];
#pragma unroll
        for (int w = 1; w < 5; w++) m0 = fmaxf(m0, p[w * 256]);
        float m1 = p[5 * 256];
#pragma unroll
        for (int w = 6; w < 10; w++) m1 = fmaxf(m1, p[w * 256]);
        pooled[r * PSTR + c * 2]     = m0;
        pooled[r * PSTR + c * 2 + 1] = m1;
    }
    __syncthreads();

    // fc1 + relu + fc2: thread -> (row r, j quad)
    const int r  = tid >> 4;
    const int j0 = (tid & 15) * 4;
    const float* pr = pooled + r * PSTR;

    float4 bq = *(const float4*)(fc1b + j0);
    float a0 = bq.x, a1 = bq.y, a2 = bq.z, a3 = bq.w;
    for (int k = 0; k < 512; k += 4) {
        float4 pv = *(const float4*)(pr + k);
        float4 w0 = *(const float4*)(fc1t_s + (k    ) * 64 + j0);
        float4 w1 = *(const float4*)(fc1t_s + (k + 1) * 64 + j0);
        float4 w2 = *(const float4*)(fc1t_s + (k + 2) * 64 + j0);
        float4 w3 = *(const float4*)(fc1t_s + (k + 3) * 64 + j0);
        a0 = fmaf(pv.x, w0.x, a0); a1 = fmaf(pv.x, w0.y, a1);
        a2 = fmaf(pv.x, w0.z, a2); a3 = fmaf(pv.x, w0.w, a3);
        a0 = fmaf(pv.y, w1.x, a0); a1 = fmaf(pv.y, w1.y, a1);
        a2 = fmaf(pv.y, w1.z, a2); a3 = fmaf(pv.y, w1.w, a3);
        a0 = fmaf(pv.z, w2.x, a0); a1 = fmaf(pv.z, w2.y, a1);
        a2 = fmaf(pv.z, w2.z, a2); a3 = fmaf(pv.z, w2.w, a3);
        a0 = fmaf(pv.w, w3.x, a0); a1 = fmaf(pv.w, w3.y, a1);
        a2 = fmaf(pv.w, w3.z, a2); a3 = fmaf(pv.w, w3.w, a3);
    }
    float4 f2 = *(const float4*)(fc2w + j0);
    float v = fmaxf(a0, 0.0f) * f2.x + fmaxf(a1, 0.0f) * f2.y
            + fmaxf(a2, 0.0f) * f2.z + fmaxf(a3, 0.0f) * f2.w;

#pragma unroll
    for (int off = 8; off > 0; off >>= 1)
        v += __shfl_xor_sync(0xffffffffu, v, off);
    if ((tid & 15) == 0) out[b0 + r] = v + fc2b[0];
}

// ---------------------------------------------------------------------------
// Launch
// ---------------------------------------------------------------------------
extern "C" void kernel_launch(void* const* d_in, const int* in_sizes, int n_in,
                              void* d_out, int out_size)
{
    (void)in_sizes; (void)n_in; (void)out_size;
    const float* x     = (const float*)d_in[0];
    const float* fc1_b = (const float*)d_in[18];
    const float* fc2_w = (const float*)d_in[19];
    const float* fc2_b = (const float*)d_in[20];
    float* out = (float*)d_out;

    uint4 *WF1, *WF2;
    float *BC1, *BC2, *O2, *FC1T;
    uint  *O1;
    cudaGetSymbolAddress((void**)&WF1,  g_Wf1);
    cudaGetSymbolAddress((void**)&WF2,  g_Wf2);
    cudaGetSymbolAddress((void**)&BC1,  g_Bc1);
    cudaGetSymbolAddress((void**)&BC2,  g_Bc2);
    cudaGetSymbolAddress((void**)&O1,   g_O1);
    cudaGetSymbolAddress((void**)&O2,   g_O2);
    cudaGetSymbolAddress((void**)&FC1T, g_FC1T);

    prep_all<<<296, 256>>>((const float*)d_in[1],  (const float*)d_in[2],
                           (const float*)d_in[3],  (const float*)d_in[4],
                           (const float*)d_in[5],  (const float*)d_in[6],
                           (const float*)d_in[7],  (const float*)d_in[8],
                           (const float*)d_in[9],  (const float*)d_in[10],
                           (const float*)d_in[11], (const float*)d_in[12],
                           (const float*)d_in[13], (const float*)d_in[14],
                           (const float*)d_in[15], (const float*)d_in[16],
                           (const float*)d_in[17],
                           WF1, BC1, WF2, BC2, FC1T);

    // SMEM: A_hi + A_lo + 2x32KB weight ring + 512-float bias + 2 mbarriers
    const int smem1 = 64 * 328 * 2 * 2 + 2 * 2048 * 16 + 512 * 4 + 16;  // 151,568
    const int smem2 = 64 * 392 * 2 * 2 + 2 * 2048 * 16 + 512 * 4 + 16;  // 167,952
    cudaFuncSetAttribute(lstm_mma<184, 192, 20, 1>,
                         cudaFuncAttributeMaxDynamicSharedMemorySize, smem1);
    cudaFuncSetAttribute(lstm_mma<256, 256, 24, 0>,
                         cudaFuncAttributeMaxDynamicSharedMemorySize, smem2);

    dim3 grid(BATCH / 64, 2);
    lstm_mma<184, 192, 20, 1><<<grid, 512, smem1>>>(x,  WF1, BC1, O1);
    lstm_mma<256, 256, 24, 0><<<grid, 512, smem2>>>(O1, WF2, BC2, O2);

    const int smem_h = 512 * 64 * 4 + HROWS * PSTR * 4;  // 197,120
    cudaFuncSetAttribute(head_kernel,
                         cudaFuncAttributeMaxDynamicSharedMemorySize, smem_h);
    head_kernel<<<BATCH / HROWS, 512, smem_h>>>(O2, FC1T, fc1_b, fc2_w, fc2_b, out);
}